// round 2
// baseline (speedup 1.0000x reference)
#include <cuda_runtime.h>

// ResidualVQ eval forward, GB300 sm_103a — Round 1 fp32 baseline.
// quantized_out = x - residual_final; commit via distance identity;
// per-layer: fused GEMM+argmin -> hist+commit-sum -> perplexity -> residual update.

#define N_DIM 32
#define C_DIM 512
#define T_DIM 2048
#define K_CODES 512
#define Q_LAYERS 6
#define P_PTS (N_DIM * T_DIM)                 // 65536
#define QUANT_ELEMS (N_DIM * C_DIM * T_DIM)   // 33554432
#define IDX_ELEMS (P_PTS * Q_LAYERS)          // 393216

// -------- scratch (device globals; no allocation allowed) --------
__device__ float  g_resid[QUANT_ELEMS];       // residual, [n, c, t] layout (same as x)
__device__ float  g_minv[P_PTS];              // per-point min distance (current layer)
__device__ int    g_idx[Q_LAYERS * P_PTS];    // argmin code per layer per point
__device__ float  g_cbnorm[Q_LAYERS * K_CODES];
__device__ int    g_hist[K_CODES];
__device__ double g_commit_accum;
__device__ double g_loss_total;
__device__ double g_perp_total;

// -------- init --------
__global__ void init_kernel() {
    int t = threadIdx.x;
    if (t < K_CODES) g_hist[t] = 0;
    if (t == 0) { g_commit_accum = 0.0; g_loss_total = 0.0; g_perp_total = 0.0; }
}

__global__ void copy_resid_kernel(const float* __restrict__ x) {
    const float4* xs = (const float4*)x;
    float4* rs = (float4*)g_resid;
    const int n4 = QUANT_ELEMS / 4;
    for (int i = blockIdx.x * blockDim.x + threadIdx.x; i < n4; i += gridDim.x * blockDim.x)
        rs[i] = xs[i];
}

// one warp per codebook row: ||c_k||^2 for all Q*K rows
__global__ void cbnorm_kernel(const float* __restrict__ cb) {
    int gw = (blockIdx.x * blockDim.x + threadIdx.x) >> 5;
    int lane = threadIdx.x & 31;
    if (gw >= Q_LAYERS * K_CODES) return;
    const float* row = cb + (size_t)gw * C_DIM;
    float s = 0.f;
    for (int c = lane; c < C_DIM; c += 32) {
        float v = row[c];
        s = fmaf(v, v, s);
    }
#pragma unroll
    for (int o = 16; o; o >>= 1) s += __shfl_xor_sync(0xffffffffu, s, o);
    if (lane == 0) g_cbnorm[gw] = s;
}

// -------- fused distance GEMM + argmin --------
// Block: 128 points (one n, 128 contiguous t) x all 512 codes (4 chunks of 128).
// 256 threads, 8x8 register tile each (128x128 per chunk). fp32 FMA.
struct SmemU {
    union {
        struct { float A[16][128]; float B[16][128]; } t;
        struct { float m1[16][128]; int i1[16][128]; } r;
    };
};

__global__ __launch_bounds__(256) void argmin_kernel(const float* __restrict__ cb, int q) {
    __shared__ __align__(16) SmemU sm;

    const int tid = threadIdx.x;
    const int tm = tid & 15;    // point group
    const int tn = tid >> 4;    // code group
    const int blk = blockIdx.x; // 512 blocks
    const int n  = blk >> 4;    // 16 blocks per n (T/128)
    const int tb = (blk & 15) << 7;

    const float* __restrict__ cbq = cb + (size_t)q * K_CODES * C_DIM;
    const float* __restrict__ R   = g_resid + ((size_t)n * C_DIM) * T_DIM + tb;
    const float* __restrict__ bn  = g_cbnorm + q * K_CODES;

    float m1[8]; int i1[8]; float av2[8];
#pragma unroll
    for (int j = 0; j < 8; j++) { m1[j] = 3.4e38f; i1[j] = 0; av2[j] = 0.f; }

    for (int kc = 0; kc < 4; kc++) {
        const int k0 = kc << 7;
        float acc[8][8];
#pragma unroll
        for (int a = 0; a < 8; a++)
#pragma unroll
            for (int b = 0; b < 8; b++) acc[a][b] = 0.f;

        for (int c0 = 0; c0 < C_DIM; c0 += 16) {
            __syncthreads();
            // A tile: residual rows c0..c0+15, 128 t values. 512 float4, 2/thread.
            {
                int l = tid;
#pragma unroll
                for (int r2 = 0; r2 < 2; r2++, l += 256) {
                    int row = l >> 5, col = (l & 31) << 2;
                    float4 v = *(const float4*)(R + (size_t)(c0 + row) * T_DIM + col);
                    *(float4*)&sm.t.A[row][col] = v;
                }
            }
            // B tile: codes k0..k0+127, dims c0..c0+15 (transposed into smem).
            {
                int l = tid;
#pragma unroll
                for (int r2 = 0; r2 < 2; r2++, l += 256) {
                    int k = l >> 2, c4 = (l & 3) << 2;
                    float4 v = *(const float4*)(cbq + (size_t)(k0 + k) * C_DIM + c0 + c4);
                    sm.t.B[c4 + 0][k] = v.x;
                    sm.t.B[c4 + 1][k] = v.y;
                    sm.t.B[c4 + 2][k] = v.z;
                    sm.t.B[c4 + 3][k] = v.w;
                }
            }
            __syncthreads();
#pragma unroll
            for (int cc = 0; cc < 16; cc++) {
                float ar[8], br[8];
                float4 a0 = *(const float4*)&sm.t.A[cc][tm << 2];
                float4 a1 = *(const float4*)&sm.t.A[cc][64 + (tm << 2)];
                float4 b0 = *(const float4*)&sm.t.B[cc][tn << 2];
                float4 b1 = *(const float4*)&sm.t.B[cc][64 + (tn << 2)];
                ar[0] = a0.x; ar[1] = a0.y; ar[2] = a0.z; ar[3] = a0.w;
                ar[4] = a1.x; ar[5] = a1.y; ar[6] = a1.z; ar[7] = a1.w;
                br[0] = b0.x; br[1] = b0.y; br[2] = b0.z; br[3] = b0.w;
                br[4] = b1.x; br[5] = b1.y; br[6] = b1.z; br[7] = b1.w;
                if (kc == 0) {
#pragma unroll
                    for (int p = 0; p < 8; p++) av2[p] = fmaf(ar[p], ar[p], av2[p]);
                }
#pragma unroll
                for (int p = 0; p < 8; p++)
#pragma unroll
                    for (int k = 0; k < 8; k++)
                        acc[p][k] = fmaf(ar[p], br[k], acc[p][k]);
            }
        }
        // evaluate this code chunk: v = (||r||^2 - 2*dot) + ||c||^2, same rounding
        // order as the reference's (a - 2*x@cbT) + cbnorm.
#pragma unroll
        for (int k = 0; k < 8; k++) {
            int kloc = (k < 4) ? ((tn << 2) + k) : (64 + (tn << 2) + (k - 4));
            int kg = k0 + kloc;
            float b = __ldg(bn + kg);
#pragma unroll
            for (int p = 0; p < 8; p++) {
                float v = __fadd_rn(__fsub_rn(av2[p], 2.0f * acc[p][k]), b);
                if (v < m1[p]) { m1[p] = v; i1[p] = kg; }
            }
        }
    }

    // cross-thread reduce: 16 tn-threads per point
    __syncthreads();
#pragma unroll
    for (int p = 0; p < 8; p++) {
        int pl = (p < 4) ? ((tm << 2) + p) : (64 + (tm << 2) + (p - 4));
        sm.r.m1[tn][pl] = m1[p];
        sm.r.i1[tn][pl] = i1[p];
    }
    __syncthreads();
    if (tid < 128) {
        float bm = 3.4e38f; int bi = 0x7fffffff;
        for (int j = 0; j < 16; j++) {
            float m = sm.r.m1[j][tid];
            int ii = sm.r.i1[j][tid];
            if (m < bm || (m == bm && ii < bi)) { bm = m; bi = ii; }
        }
        int gi = n * T_DIM + tb + tid;
        g_idx[q * P_PTS + gi] = bi;
        g_minv[gi] = bm;
    }
}

// -------- histogram + commit sum --------
__global__ void hist_sum_kernel(int q) {
    __shared__ int h[K_CODES];
    __shared__ float ws[8];
    int tid = threadIdx.x;
    for (int i = tid; i < K_CODES; i += 256) h[i] = 0;
    __syncthreads();
    float s = 0.f;
    for (int i = blockIdx.x * 256 + tid; i < P_PTS; i += gridDim.x * 256) {
        atomicAdd(&h[g_idx[q * P_PTS + i]], 1);
        s += g_minv[i];
    }
    __syncthreads();
#pragma unroll
    for (int o = 16; o; o >>= 1) s += __shfl_xor_sync(0xffffffffu, s, o);
    if ((tid & 31) == 0) ws[tid >> 5] = s;
    __syncthreads();
    if (tid < 8) {
        float v = ws[tid];
#pragma unroll
        for (int o = 4; o; o >>= 1) v += __shfl_xor_sync(0xffu, v, o);
        if (tid == 0) atomicAdd(&g_commit_accum, (double)v);
    }
    for (int i = tid; i < K_CODES; i += 256) {
        int c = h[i];
        if (c) atomicAdd(&g_hist[i], c);
    }
}

// -------- perplexity + commit finalize (1 block, 512 threads) --------
__global__ void perp_commit_kernel() {
    __shared__ float red[K_CODES];
    int t = threadIdx.x;
    float cnt = (float)g_hist[t];
    float prob = cnt * (1.0f / 65536.0f);    // sum(counts) == P_PTS exactly
    red[t] = prob * logf(prob + 1e-7f);
    __syncthreads();
    for (int o = 256; o; o >>= 1) {
        if (t < o) red[t] += red[t + o];
        __syncthreads();
    }
    if (t == 0) {
        g_perp_total += (double)expf(-red[0]);
        g_loss_total += g_commit_accum * (1.0 / ((double)P_PTS * (double)C_DIM));
        g_commit_accum = 0.0;
    }
    g_hist[t] = 0;   // each thread resets its own slot (read before reduction)
}

// -------- residual update: r -= cb[idx] --------
__global__ void update_kernel(const float* __restrict__ cb, int q) {
    int gp = blockIdx.x * blockDim.x + threadIdx.x;  // point id 0..65535
    int n = gp >> 11;
    int t = gp & 2047;
    int idx = g_idx[q * P_PTS + gp];
    const float4* crow = (const float4*)(cb + (size_t)q * K_CODES * C_DIM + (size_t)idx * C_DIM);
    float* R = g_resid + ((size_t)n * C_DIM) * T_DIM + t;
    for (int c = 0; c < C_DIM; c += 4) {
        float4 cv = __ldg(&crow[c >> 2]);
        size_t o0 = (size_t)c * T_DIM;
        R[o0]             -= cv.x;
        R[o0 + T_DIM]     -= cv.y;
        R[o0 + 2 * T_DIM] -= cv.z;
        R[o0 + 3 * T_DIM] -= cv.w;
    }
}

// -------- finalize outputs --------
__global__ void finalize_quant_kernel(const float* __restrict__ x, float* __restrict__ out) {
    const float4* xs = (const float4*)x;
    const float4* rs = (const float4*)g_resid;
    float4* os = (float4*)out;
    const int n4 = QUANT_ELEMS / 4;
    for (int i = blockIdx.x * blockDim.x + threadIdx.x; i < n4; i += gridDim.x * blockDim.x) {
        float4 a = xs[i], b = rs[i];
        os[i] = make_float4(a.x - b.x, a.y - b.y, a.z - b.z, a.w - b.w);
    }
}

__global__ void finalize_idx_kernel(float* __restrict__ out) {
    for (int j = blockIdx.x * blockDim.x + threadIdx.x; j < IDX_ELEMS; j += gridDim.x * blockDim.x) {
        int p = j / Q_LAYERS;
        int q = j - p * Q_LAYERS;    // layout [n, t, q] row-major
        out[QUANT_ELEMS + j] = (float)g_idx[q * P_PTS + p];
    }
}

__global__ void finalize_scalar_kernel(float* __restrict__ out) {
    out[QUANT_ELEMS + IDX_ELEMS]     = (float)(g_loss_total * (1.0 / Q_LAYERS));
    out[QUANT_ELEMS + IDX_ELEMS + 1] = (float)(g_perp_total * (1.0 / Q_LAYERS));
}

extern "C" void kernel_launch(void* const* d_in, const int* in_sizes, int n_in,
                              void* d_out, int out_size) {
    const float* x  = (const float*)d_in[0];   // [32, 512, 2048]
    const float* cb = (const float*)d_in[1];   // [6, 512, 512]
    float* out = (float*)d_out;

    init_kernel<<<1, 512>>>();
    copy_resid_kernel<<<2048, 256>>>(x);
    cbnorm_kernel<<<384, 256>>>(cb);

    for (int q = 0; q < Q_LAYERS; q++) {
        argmin_kernel<<<512, 256>>>(cb, q);
        hist_sum_kernel<<<64, 256>>>(q);
        perp_commit_kernel<<<1, 512>>>();
        update_kernel<<<256, 256>>>(cb, q);
    }

    finalize_quant_kernel<<<2048, 256>>>(x, out);
    finalize_idx_kernel<<<384, 256>>>(out);
    finalize_scalar_kernel<<<1, 1>>>(out);
}

// round 5
// speedup vs baseline: 1.0977x; 1.0977x over previous
#include <cuda_runtime.h>
#include <cstdint>

// ResidualVQ eval forward — Round 4: packed-fp32 (fma.rn.f32x2 / FFMA2) GEMM.
// (R3 resubmit — R3/R4 bench attempt died to infra, kernel never ran.)
// tcgen05 unavailable (harness ptxas targets plain sm_103); FFMA2 doubles
// the fp32 FMA roofline instead. Numerics identical to R1 (rel_err 2.26e-7).

#define N_DIM 32
#define C_DIM 512
#define T_DIM 2048
#define K_CODES 512
#define Q_LAYERS 6
#define P_PTS (N_DIM * T_DIM)                 // 65536
#define QUANT_ELEMS (N_DIM * C_DIM * T_DIM)   // 33554432
#define IDX_ELEMS (P_PTS * Q_LAYERS)          // 393216

// -------- scratch --------
__device__ float  g_resid[QUANT_ELEMS];       // residual, [n, c, t]
__device__ float  g_minv[P_PTS];
__device__ int    g_idx[Q_LAYERS * P_PTS];
__device__ float  g_cbnorm[Q_LAYERS * K_CODES];
__device__ int    g_hist[K_CODES];
__device__ double g_commit_accum;
__device__ double g_loss_total;
__device__ double g_perp_total;

// -------- packed fp32 helpers --------
__device__ __forceinline__ void ffma2(unsigned long long& d,
                                      unsigned long long a,
                                      unsigned long long b) {
    asm("fma.rn.f32x2 %0, %1, %2, %0;" : "+l"(d) : "l"(a), "l"(b));
}
__device__ __forceinline__ float2 upk2(unsigned long long v) {
    float2 r; asm("mov.b64 {%0, %1}, %2;" : "=f"(r.x), "=f"(r.y) : "l"(v));
    return r;
}

// -------- init --------
__global__ void init_kernel() {
    int t = threadIdx.x;
    if (t < K_CODES) g_hist[t] = 0;
    if (t == 0) { g_commit_accum = 0.0; g_loss_total = 0.0; g_perp_total = 0.0; }
}

__global__ void copy_resid_kernel(const float* __restrict__ x) {
    const float4* xs = (const float4*)x;
    float4* rs = (float4*)g_resid;
    const int n4 = QUANT_ELEMS / 4;
    for (int i = blockIdx.x * blockDim.x + threadIdx.x; i < n4; i += gridDim.x * blockDim.x)
        rs[i] = xs[i];
}

__global__ void cbnorm_kernel(const float* __restrict__ cb) {
    int gw = (blockIdx.x * blockDim.x + threadIdx.x) >> 5;
    int lane = threadIdx.x & 31;
    if (gw >= Q_LAYERS * K_CODES) return;
    const float* row = cb + (size_t)gw * C_DIM;
    float s = 0.f;
    for (int c = lane; c < C_DIM; c += 32) { float v = row[c]; s = fmaf(v, v, s); }
#pragma unroll
    for (int o = 16; o; o >>= 1) s += __shfl_xor_sync(0xffffffffu, s, o);
    if (lane == 0) g_cbnorm[gw] = s;
}

// -------- fused distance GEMM + argmin (FFMA2, double-buffered) --------
// Block: 128 t-points x 512 codes (4 chunks of 128). 256 threads.
// Thread tile: 8 points (4 f32x2 pairs) x 8 codes. B stored duplicated in smem
// so b64 operands load directly (zero pack instructions).
struct SmemPipe {
    float A[2][16][128];    // [stage][c][t]        16 KB
    float B2[2][16][256];   // [stage][c][2*code]   32 KB (duplicated values)
};
union SmU {
    SmemPipe p;
    struct { float m1[16][128]; int i1[16][128]; } r;
};

template <bool FIRST>
__device__ __forceinline__ void mma_tile(const SmU& sm, int buf, int tm, int tn,
                                         unsigned long long acc[4][8],
                                         unsigned long long av2p[4]) {
#pragma unroll
    for (int cc = 0; cc < 16; cc++) {
        ulonglong2 al = *(const ulonglong2*)&sm.p.A[buf][cc][tm << 2];
        ulonglong2 ah = *(const ulonglong2*)&sm.p.A[buf][cc][64 + (tm << 2)];
        ulonglong2 b0 = *(const ulonglong2*)&sm.p.B2[buf][cc][tn << 3];
        ulonglong2 b1 = *(const ulonglong2*)&sm.p.B2[buf][cc][(tn << 3) + 4];
        ulonglong2 b2 = *(const ulonglong2*)&sm.p.B2[buf][cc][128 + (tn << 3)];
        ulonglong2 b3 = *(const ulonglong2*)&sm.p.B2[buf][cc][128 + (tn << 3) + 4];
        unsigned long long ap0 = al.x, ap1 = al.y, ap2 = ah.x, ap3 = ah.y;
        if (FIRST) {
            ffma2(av2p[0], ap0, ap0);
            ffma2(av2p[1], ap1, ap1);
            ffma2(av2p[2], ap2, ap2);
            ffma2(av2p[3], ap3, ap3);
        }
        ffma2(acc[0][0], ap0, b0.x); ffma2(acc[0][1], ap0, b0.y);
        ffma2(acc[0][2], ap0, b1.x); ffma2(acc[0][3], ap0, b1.y);
        ffma2(acc[0][4], ap0, b2.x); ffma2(acc[0][5], ap0, b2.y);
        ffma2(acc[0][6], ap0, b3.x); ffma2(acc[0][7], ap0, b3.y);
        ffma2(acc[1][0], ap1, b0.x); ffma2(acc[1][1], ap1, b0.y);
        ffma2(acc[1][2], ap1, b1.x); ffma2(acc[1][3], ap1, b1.y);
        ffma2(acc[1][4], ap1, b2.x); ffma2(acc[1][5], ap1, b2.y);
        ffma2(acc[1][6], ap1, b3.x); ffma2(acc[1][7], ap1, b3.y);
        ffma2(acc[2][0], ap2, b0.x); ffma2(acc[2][1], ap2, b0.y);
        ffma2(acc[2][2], ap2, b1.x); ffma2(acc[2][3], ap2, b1.y);
        ffma2(acc[2][4], ap2, b2.x); ffma2(acc[2][5], ap2, b2.y);
        ffma2(acc[2][6], ap2, b3.x); ffma2(acc[2][7], ap2, b3.y);
        ffma2(acc[3][0], ap3, b0.x); ffma2(acc[3][1], ap3, b0.y);
        ffma2(acc[3][2], ap3, b1.x); ffma2(acc[3][3], ap3, b1.y);
        ffma2(acc[3][4], ap3, b2.x); ffma2(acc[3][5], ap3, b2.y);
        ffma2(acc[3][6], ap3, b3.x); ffma2(acc[3][7], ap3, b3.y);
    }
}

__global__ __launch_bounds__(256) void argmin_kernel(const float* __restrict__ cb, int q) {
    __shared__ __align__(16) SmU sm;

    const int tid = threadIdx.x;
    const int tm = tid & 15;    // point group
    const int tn = tid >> 4;    // code group
    const int blk = blockIdx.x; // 512 blocks
    const int n  = blk >> 4;
    const int tb = (blk & 15) << 7;

    const float* __restrict__ cbq = cb + (size_t)q * K_CODES * C_DIM;
    const float* __restrict__ R   = g_resid + ((size_t)n * C_DIM) * T_DIM + tb;
    const float* __restrict__ bn  = g_cbnorm + q * K_CODES;

    // fixed per-thread load coordinates
    const int rA0 = tid >> 5,        cA0 = (tid & 31) << 2;
    const int rA1 = (tid + 256) >> 5;                         // cA1 == cA0
    const int kB0 = tid >> 2,        cB0 = (tid & 3) << 2;
    const int kB1 = (tid + 256) >> 2;                         // cB1 == cB0

    unsigned long long acc[4][8];
    unsigned long long av2p[4];
    float m1[8]; int i1[8];
#pragma unroll
    for (int pr = 0; pr < 4; pr++) {
        av2p[pr] = 0ull;
#pragma unroll
        for (int k = 0; k < 8; k++) acc[pr][k] = 0ull;
    }
#pragma unroll
    for (int p = 0; p < 8; p++) { m1[p] = 3.4e38f; i1[p] = 0; }

    // ---- preload tile 0 (kc=0, c0=0) into stage 0 ----
    {
        float4 pa0 = *(const float4*)(R + (size_t)rA0 * T_DIM + cA0);
        float4 pa1 = *(const float4*)(R + (size_t)rA1 * T_DIM + cA0);
        float4 pb0 = *(const float4*)(cbq + (size_t)kB0 * C_DIM + cB0);
        float4 pb1 = *(const float4*)(cbq + (size_t)kB1 * C_DIM + cB0);
        *(float4*)&sm.p.A[0][rA0][cA0] = pa0;
        *(float4*)&sm.p.A[0][rA1][cA0] = pa1;
        *(float2*)&sm.p.B2[0][cB0 + 0][2 * kB0] = make_float2(pb0.x, pb0.x);
        *(float2*)&sm.p.B2[0][cB0 + 1][2 * kB0] = make_float2(pb0.y, pb0.y);
        *(float2*)&sm.p.B2[0][cB0 + 2][2 * kB0] = make_float2(pb0.z, pb0.z);
        *(float2*)&sm.p.B2[0][cB0 + 3][2 * kB0] = make_float2(pb0.w, pb0.w);
        *(float2*)&sm.p.B2[0][cB0 + 0][2 * kB1] = make_float2(pb1.x, pb1.x);
        *(float2*)&sm.p.B2[0][cB0 + 1][2 * kB1] = make_float2(pb1.y, pb1.y);
        *(float2*)&sm.p.B2[0][cB0 + 2][2 * kB1] = make_float2(pb1.z, pb1.z);
        *(float2*)&sm.p.B2[0][cB0 + 3][2 * kB1] = make_float2(pb1.w, pb1.w);
    }
    __syncthreads();

    // ---- main pipeline: 128 tiles = 4 code-chunks x 32 c-tiles ----
    int buf = 0;
    for (int it = 0; it < 128; it++) {
        const int kc = it >> 5;
        const int nit = it + 1;
        const bool hasn = (nit < 128);
        float4 pa0, pa1, pb0, pb1;
        if (hasn) {
            const int nkc = nit >> 5, c0n = (nit & 31) << 4;
            pa0 = *(const float4*)(R + (size_t)(c0n + rA0) * T_DIM + cA0);
            pa1 = *(const float4*)(R + (size_t)(c0n + rA1) * T_DIM + cA0);
            const float* bq = cbq + (size_t)(nkc << 7) * C_DIM + c0n;
            pb0 = *(const float4*)(bq + (size_t)kB0 * C_DIM + cB0);
            pb1 = *(const float4*)(bq + (size_t)kB1 * C_DIM + cB0);
        }

        if (kc == 0) mma_tile<true >(sm, buf, tm, tn, acc, av2p);
        else         mma_tile<false>(sm, buf, tm, tn, acc, av2p);

        if (hasn) {
            const int nb = buf ^ 1;
            *(float4*)&sm.p.A[nb][rA0][cA0] = pa0;
            *(float4*)&sm.p.A[nb][rA1][cA0] = pa1;
            *(float2*)&sm.p.B2[nb][cB0 + 0][2 * kB0] = make_float2(pb0.x, pb0.x);
            *(float2*)&sm.p.B2[nb][cB0 + 1][2 * kB0] = make_float2(pb0.y, pb0.y);
            *(float2*)&sm.p.B2[nb][cB0 + 2][2 * kB0] = make_float2(pb0.z, pb0.z);
            *(float2*)&sm.p.B2[nb][cB0 + 3][2 * kB0] = make_float2(pb0.w, pb0.w);
            *(float2*)&sm.p.B2[nb][cB0 + 0][2 * kB1] = make_float2(pb1.x, pb1.x);
            *(float2*)&sm.p.B2[nb][cB0 + 1][2 * kB1] = make_float2(pb1.y, pb1.y);
            *(float2*)&sm.p.B2[nb][cB0 + 2][2 * kB1] = make_float2(pb1.z, pb1.z);
            *(float2*)&sm.p.B2[nb][cB0 + 3][2 * kB1] = make_float2(pb1.w, pb1.w);
        }
        __syncthreads();

        // end of a code chunk: evaluate distances, update argmin, reset acc
        if ((it & 31) == 31) {
            const int k0 = kc << 7;
#pragma unroll
            for (int k = 0; k < 8; k++) {
                const int kloc = (k < 4) ? ((tn << 2) + k) : (64 + (tn << 2) + (k - 4));
                const int kg = k0 + kloc;
                const float b = __ldg(bn + kg);
#pragma unroll
                for (int pr = 0; pr < 4; pr++) {
                    float2 d  = upk2(acc[pr][k]);
                    float2 n2 = upk2(av2p[pr]);
                    float v0 = __fadd_rn(__fsub_rn(n2.x, 2.0f * d.x), b);
                    float v1 = __fadd_rn(__fsub_rn(n2.y, 2.0f * d.y), b);
                    const int p0i = pr * 2, p1i = pr * 2 + 1;
                    if (v0 < m1[p0i]) { m1[p0i] = v0; i1[p0i] = kg; }
                    if (v1 < m1[p1i]) { m1[p1i] = v1; i1[p1i] = kg; }
                    acc[pr][k] = 0ull;
                }
            }
        }
        buf ^= 1;
    }

    // cross-thread reduce: 16 tn-threads per point (same mapping as R1)
    __syncthreads();
#pragma unroll
    for (int p = 0; p < 8; p++) {
        const int pl = (p < 4) ? ((tm << 2) + p) : (64 + (tm << 2) + (p - 4));
        sm.r.m1[tn][pl] = m1[p];
        sm.r.i1[tn][pl] = i1[p];
    }
    __syncthreads();
    if (tid < 128) {
        float bm = 3.4e38f; int bi = 0x7fffffff;
        for (int j = 0; j < 16; j++) {
            float m = sm.r.m1[j][tid];
            int ii = sm.r.i1[j][tid];
            if (m < bm || (m == bm && ii < bi)) { bm = m; bi = ii; }
        }
        int gi = n * T_DIM + tb + tid;
        g_idx[q * P_PTS + gi] = bi;
        g_minv[gi] = bm;
    }
}

// -------- histogram + commit sum --------
__global__ void hist_sum_kernel(int q) {
    __shared__ int h[K_CODES];
    __shared__ float ws[8];
    int tid = threadIdx.x;
    for (int i = tid; i < K_CODES; i += 256) h[i] = 0;
    __syncthreads();
    float s = 0.f;
    for (int i = blockIdx.x * 256 + tid; i < P_PTS; i += gridDim.x * 256) {
        atomicAdd(&h[g_idx[q * P_PTS + i]], 1);
        s += g_minv[i];
    }
    __syncthreads();
#pragma unroll
    for (int o = 16; o; o >>= 1) s += __shfl_xor_sync(0xffffffffu, s, o);
    if ((tid & 31) == 0) ws[tid >> 5] = s;
    __syncthreads();
    if (tid < 8) {
        float v = ws[tid];
#pragma unroll
        for (int o = 4; o; o >>= 1) v += __shfl_xor_sync(0xffu, v, o);
        if (tid == 0) atomicAdd(&g_commit_accum, (double)v);
    }
    for (int i = tid; i < K_CODES; i += 256) {
        int c = h[i];
        if (c) atomicAdd(&g_hist[i], c);
    }
}

// -------- perplexity + commit finalize --------
__global__ void perp_commit_kernel() {
    __shared__ float red[K_CODES];
    int t = threadIdx.x;
    float cnt = (float)g_hist[t];
    float prob = cnt * (1.0f / 65536.0f);
    red[t] = prob * logf(prob + 1e-7f);
    __syncthreads();
    for (int o = 256; o; o >>= 1) {
        if (t < o) red[t] += red[t + o];
        __syncthreads();
    }
    if (t == 0) {
        g_perp_total += (double)expf(-red[0]);
        g_loss_total += g_commit_accum * (1.0 / ((double)P_PTS * (double)C_DIM));
        g_commit_accum = 0.0;
    }
    g_hist[t] = 0;
}

// -------- residual update --------
__global__ void update_kernel(const float* __restrict__ cb, int q) {
    int gp = blockIdx.x * blockDim.x + threadIdx.x;
    int n = gp >> 11;
    int t = gp & 2047;
    int idx = g_idx[q * P_PTS + gp];
    const float4* crow = (const float4*)(cb + (size_t)q * K_CODES * C_DIM + (size_t)idx * C_DIM);
    float* R = g_resid + ((size_t)n * C_DIM) * T_DIM + t;
    for (int c = 0; c < C_DIM; c += 4) {
        float4 cv = __ldg(&crow[c >> 2]);
        size_t o0 = (size_t)c * T_DIM;
        R[o0]             -= cv.x;
        R[o0 + T_DIM]     -= cv.y;
        R[o0 + 2 * T_DIM] -= cv.z;
        R[o0 + 3 * T_DIM] -= cv.w;
    }
}

// -------- finalize outputs --------
__global__ void finalize_quant_kernel(const float* __restrict__ x, float* __restrict__ out) {
    const float4* xs = (const float4*)x;
    const float4* rs = (const float4*)g_resid;
    float4* os = (float4*)out;
    const int n4 = QUANT_ELEMS / 4;
    for (int i = blockIdx.x * blockDim.x + threadIdx.x; i < n4; i += gridDim.x * blockDim.x) {
        float4 a = xs[i], b = rs[i];
        os[i] = make_float4(a.x - b.x, a.y - b.y, a.z - b.z, a.w - b.w);
    }
}

__global__ void finalize_idx_kernel(float* __restrict__ out) {
    for (int j = blockIdx.x * blockDim.x + threadIdx.x; j < IDX_ELEMS; j += gridDim.x * blockDim.x) {
        int p = j / Q_LAYERS;
        int q = j - p * Q_LAYERS;
        out[QUANT_ELEMS + j] = (float)g_idx[q * P_PTS + p];
    }
}

__global__ void finalize_scalar_kernel(float* __restrict__ out) {
    out[QUANT_ELEMS + IDX_ELEMS]     = (float)(g_loss_total * (1.0 / Q_LAYERS));
    out[QUANT_ELEMS + IDX_ELEMS + 1] = (float)(g_perp_total * (1.0 / Q_LAYERS));
}

extern "C" void kernel_launch(void* const* d_in, const int* in_sizes, int n_in,
                              void* d_out, int out_size) {
    const float* x  = (const float*)d_in[0];   // [32, 512, 2048]
    const float* cb = (const float*)d_in[1];   // [6, 512, 512]
    float* out = (float*)d_out;

    init_kernel<<<1, 512>>>();
    copy_resid_kernel<<<2048, 256>>>(x);
    cbnorm_kernel<<<384, 256>>>(cb);

    for (int q = 0; q < Q_LAYERS; q++) {
        argmin_kernel<<<512, 256>>>(cb, q);
        hist_sum_kernel<<<64, 256>>>(q);
        perp_commit_kernel<<<1, 512>>>();
        update_kernel<<<256, 256>>>(cb, q);
    }

    finalize_quant_kernel<<<2048, 256>>>(x, out);
    finalize_idx_kernel<<<384, 256>>>(out);
    finalize_scalar_kernel<<<1, 1>>>(out);
}